// round 4
// baseline (speedup 1.0000x reference)
#include <cuda_runtime.h>
#include <cstdint>

// Problem constants
#define N_TOK 16384
#define C_DIM 2048
#define E_DIM 64
#define CAP   640            // int(1.25 * 16384 * 2 / 64)

#define TOK_PER_CTA 64
#define KT 64                // K tile
#define NCTA (N_TOK / TOK_PER_CTA)   // 256

// Output layout (float32):
//   [0, N*E*2)        dispatch_mask [N,E,2]
//   [N*E*2, 2*N*E*2)  combine_weights [N,E,2]
//   [2*N*E*2]         aux_loss
//   [2*N*E*2 + 1]     z_loss
#define DISP_OFF  ((size_t)0)
#define COMB_OFF  ((size_t)N_TOK * E_DIM * 2)
#define AUX_OFF   ((size_t)2 * N_TOK * E_DIM * 2)
#define Z_OFF     (AUX_OFF + 1)

// ---------------- scratch (static device globals; no allocs) ----------------
__device__ float    g_Wt[C_DIM * E_DIM];        // W transposed: [k][e]
__device__ uint32_t g_t2i[N_TOK];               // e1 | e2<<8
__device__ float2   g_t2v[N_TOK];               // top2 gate values
__device__ uint32_t g_rank[N_TOK];              // local rank: r0 | r1<<16
__device__ int      g_counts[NCTA * 128];       // per-block bin counts (bin = k*64+e)
__device__ int      g_off[NCTA * 128];          // exclusive scan across blocks
__device__ float    g_mepart[NCTA * E_DIM];     // per-block expert gate sums
__device__ float    g_zpart[NCTA];              // per-block sum of logits^2

// ---------------- K0: transpose W [E,C] -> Wt [C,E] ----------------
__global__ void k_transpose(const float* __restrict__ W) {
    int idx = blockIdx.x * 256 + threadIdx.x;   // 131072 total
    int e = idx >> 11;          // / 2048
    int k = idx & 2047;
    g_Wt[k * E_DIM + e] = W[idx];
}

// ---------------- K1: GEMM + softmax + top2 + local ranks ----------------
// CTA: 128 threads (4 warps), 64 tokens, all 64 experts.
// Warp w handles experts [w*16, w*16+16). Lane owns tokens (lane, lane+32).
// Accumulators are f32x2 packed along the EXPERT dimension (pairs e, e+1).
__global__ __launch_bounds__(128) void k_main(const float* __restrict__ x) {
    __shared__ __align__(16) float xs[TOK_PER_CTA * 65];   // x tile [tok][65] (padded); reused for logits/gates
    __shared__ __align__(16) float ws[KT * E_DIM];          // W tile [k][e]
    __shared__ float sinv_s[TOK_PER_CTA];
    __shared__ float zrow[TOK_PER_CTA];
    __shared__ int   cnt[2 * 128];                          // per-warp per-bin counts

    const int tid  = threadIdx.x;
    const int lane = tid & 31;
    const int w    = tid >> 5;
    const int cta  = blockIdx.x;
    const int e0   = w * 16;
    const float* xblk = x + (size_t)cta * TOK_PER_CTA * C_DIM;

    unsigned long long acc[16];   // [0..7] = token lane, [8..15] = token lane+32
#pragma unroll
    for (int i = 0; i < 16; i++) acc[i] = 0ull;

    const int row0 = lane * 65;
    const int row1 = (lane + 32) * 65;

    for (int kt = 0; kt < C_DIM; kt += KT) {
        // ---- load x tile: 2 threads per token, each 32 consecutive floats ----
        {
            int t = tid >> 1;
            int half = tid & 1;
            const float4* src = (const float4*)(xblk + (size_t)t * C_DIM + kt + half * 32);
            float* dst = xs + t * 65 + half * 32;
#pragma unroll
            for (int i = 0; i < 8; i++) {
                float4 v = src[i];
                dst[4*i+0] = v.x; dst[4*i+1] = v.y; dst[4*i+2] = v.z; dst[4*i+3] = v.w;
            }
        }
        // ---- load W tile: KT*64 floats = 1024 float4 ----
        {
            const float4* src = (const float4*)(g_Wt + (size_t)kt * E_DIM);
            float4* dst = (float4*)ws;
#pragma unroll
            for (int i = 0; i < 8; i++) dst[tid + i * 128] = src[tid + i * 128];
        }
        __syncthreads();

#pragma unroll 2
        for (int k = 0; k < KT; k++) {
            float xa = xs[row0 + k];
            float xb = xs[row1 + k];
            unsigned long long xap, xbp;
            asm("mov.b64 %0, {%1, %1};" : "=l"(xap) : "f"(xa));
            asm("mov.b64 %0, {%1, %1};" : "=l"(xbp) : "f"(xb));
            const unsigned long long* wp =
                (const unsigned long long*)(ws + k * E_DIM + e0);
#pragma unroll
            for (int p = 0; p < 8; p++) {
                unsigned long long b = wp[p];
                asm("fma.rn.f32x2 %0, %1, %2, %0;" : "+l"(acc[p])     : "l"(xap), "l"(b));
                asm("fma.rn.f32x2 %0, %1, %2, %0;" : "+l"(acc[8 + p]) : "l"(xbp), "l"(b));
            }
        }
        __syncthreads();
    }

    // ---- write logits into xs (reused) ----
#pragma unroll
    for (int p = 0; p < 8; p++) {
        xs[row0 + e0 + 2*p]     = __uint_as_float((unsigned)(acc[p] & 0xffffffffull));
        xs[row0 + e0 + 2*p + 1] = __uint_as_float((unsigned)(acc[p] >> 32));
        xs[row1 + e0 + 2*p]     = __uint_as_float((unsigned)(acc[8+p] & 0xffffffffull));
        xs[row1 + e0 + 2*p + 1] = __uint_as_float((unsigned)(acc[8+p] >> 32));
    }
    // Zero ALL 256 count bins (both warps' halves). Previously only the first
    // 128 were zeroed -> stale SMEM on graph replays -> nondeterministic output.
    cnt[tid] = 0;
    cnt[128 + tid] = 0;
    __syncthreads();

    // ---- per-token softmax + top2 (threads 0..63, one token each) ----
    int i1 = 0, i2 = 0;
    int r0 = 0, r1 = 0;
    if (tid < 64) {
        float* row = xs + tid * 65;
        float m = row[0];
#pragma unroll 4
        for (int e = 1; e < E_DIM; e++) m = fmaxf(m, row[e]);
        float s = 0.f, z = 0.f;
        float b1 = -1.f, b2 = -1.f;
#pragma unroll 4
        for (int e = 0; e < E_DIM; e++) {
            float l = row[e];
            z += l * l;
            float v = expf(l - m);
            row[e] = v;            // overwrite with unnormalized gate
            s += v;
            if (v > b1)      { b2 = b1; i2 = i1; b1 = v; i1 = e; }
            else if (v > b2) { b2 = v; i2 = e; }
        }
        float sinv = 1.f / s;
        sinv_s[tid] = sinv;
        zrow[tid] = z;
        int n = cta * TOK_PER_CTA + tid;
        g_t2v[n] = make_float2(b1 * sinv, b2 * sinv);

        // ---- warp-level deterministic local ranks (token order) ----
        unsigned lt = (1u << lane) - 1u;
        unsigned m0 = __match_any_sync(0xffffffffu, i1);
        r0 = __popc(m0 & lt);
        if ((m0 & lt) == 0) cnt[w * 128 + i1] = __popc(m0);
        unsigned m1 = __match_any_sync(0xffffffffu, i2);
        r1 = __popc(m1 & lt);
        if ((m1 & lt) == 0) cnt[w * 128 + 64 + i2] = __popc(m1);
    }
    __syncthreads();

    if (tid < 64) {
        if (w == 1) {                 // second warp: add first warp's counts
            r0 += cnt[i1];
            r1 += cnt[64 + i2];
        }
        int n = cta * TOK_PER_CTA + tid;
        g_rank[n] = (uint32_t)r0 | ((uint32_t)r1 << 16);
        g_t2i[n]  = (uint32_t)i1 | ((uint32_t)i2 << 8);

        // expert gate-sum partial: sum_t gate[t][e]
        float sme = 0.f;
#pragma unroll 4
        for (int t = 0; t < TOK_PER_CTA; t++)
            sme += xs[t * 65 + tid] * sinv_s[t];
        g_mepart[cta * E_DIM + tid] = sme;
    }
    // per-block bin counts (all 128 bins)
    g_counts[cta * 128 + tid] = cnt[tid] + cnt[128 + tid];

    if (tid == 0) {
        float zz = 0.f;
        for (int t = 0; t < TOK_PER_CTA; t++) zz += zrow[t];
        g_zpart[cta] = zz;
    }
}

// ---------------- K2: cross-block scan + losses ----------------
__global__ __launch_bounds__(128) void k_scan(float* __restrict__ out) {
    int b = threadIdx.x;   // 128 bins
    __shared__ int   tot[128];
    __shared__ float red[128];

    int run = 0;
#pragma unroll 4
    for (int blk = 0; blk < NCTA; blk++) {
        int c = g_counts[blk * 128 + b];
        g_off[blk * 128 + b] = run;
        run += c;
    }
    tot[b] = run;
    __syncthreads();

    // aux = E * sum_e me[e] * ce[e]
    float a = 0.f;
    if (b < 64) {
        float me = 0.f;
        for (int blk = 0; blk < NCTA; blk++) me += g_mepart[blk * E_DIM + b];
        me *= (1.f / (float)N_TOK);
        float ce = (float)tot[b] * (1.f / (float)N_TOK);   // top-1 counts (bins 0..63)
        a = (float)E_DIM * me * ce;
    }
    red[b] = a;
    __syncthreads();
    for (int s = 64; s > 0; s >>= 1) {
        if (b < s) red[b] += red[b + s];
        __syncthreads();
    }
    if (b == 0) out[AUX_OFF] = red[0];
    __syncthreads();

    // z_loss = mean(logits^2)
    float zz = g_zpart[b] + g_zpart[b + 128];
    red[b] = zz;
    __syncthreads();
    for (int s = 64; s > 0; s >>= 1) {
        if (b < s) red[b] += red[b + s];
        __syncthreads();
    }
    if (b == 0) out[Z_OFF] = red[0] * (1.f / ((float)N_TOK * (float)E_DIM));
}

// ---------------- K3: zero + scatter outputs ----------------
__global__ __launch_bounds__(256) void k_out(float* __restrict__ out) {
    int cta = blockIdx.x;      // 256 CTAs, 64 tokens each
    int tid = threadIdx.x;

    float4 z4 = make_float4(0.f, 0.f, 0.f, 0.f);
    float4* dz = (float4*)(out + DISP_OFF + (size_t)cta * TOK_PER_CTA * 128);
    float4* cz = (float4*)(out + COMB_OFF + (size_t)cta * TOK_PER_CTA * 128);
#pragma unroll
    for (int i = 0; i < 8; i++) {
        dz[tid + i * 256] = z4;
        cz[tid + i * 256] = z4;
    }
    __syncthreads();

    if (tid < TOK_PER_CTA) {
        int n = cta * TOK_PER_CTA + tid;
        uint32_t ii = g_t2i[n];
        int e1 = ii & 0xff, e2 = (ii >> 8) & 0xff;
        uint32_t rr = g_rank[n];
        float2 vv = g_t2v[n];

        int pos0 = g_off[cta * 128 + e1]      + (int)(rr & 0xffff);
        int pos1 = g_off[cta * 128 + 64 + e2] + (int)(rr >> 16);

        size_t base = (size_t)n * 128;
        if (pos0 < CAP) {
            out[DISP_OFF + base + e1 * 2 + 0] = 1.0f;
            out[COMB_OFF + base + e1 * 2 + 0] = vv.x;
        }
        if (pos1 < CAP) {
            out[DISP_OFF + base + e2 * 2 + 1] = 1.0f;
            out[COMB_OFF + base + e2 * 2 + 1] = vv.y;
        }
    }
}

// ---------------- entry ----------------
extern "C" void kernel_launch(void* const* d_in, const int* in_sizes, int n_in,
                              void* d_out, int out_size) {
    const float* x = (const float*)d_in[0];   // [4,4096,2048] -> [16384,2048]
    const float* W = (const float*)d_in[1];   // [64,2048]
    float* out = (float*)d_out;

    k_transpose<<<(C_DIM * E_DIM) / 256, 256>>>(W);
    k_main<<<NCTA, 128>>>(x);
    k_scan<<<1, 128>>>(out);
    k_out<<<NCTA, 256>>>(out);
}

// round 5
// speedup vs baseline: 1.2470x; 1.2470x over previous
#include <cuda_runtime.h>
#include <cstdint>

// Problem constants
#define N_TOK 16384
#define C_DIM 2048
#define E_DIM 64
#define CAP   640            // int(1.25 * 16384 * 2 / 64)

#define TOK_PER_CTA 64
#define KT 64                // K tile
#define KHALF 1024           // per-group K range
#define NCTA 256             // k_main CTAs (64-token blocks)
#define XS_STRIDE 65

// Output layout (float32):
//   [0, N*E*2)        dispatch_mask [N,E,2]
//   [N*E*2, 2*N*E*2)  combine_weights [N,E,2]
//   [2*N*E*2]         aux_loss
//   [2*N*E*2 + 1]     z_loss
#define DISP_OFF  ((size_t)0)
#define COMB_OFF  ((size_t)N_TOK * E_DIM * 2)
#define AUX_OFF   ((size_t)2 * N_TOK * E_DIM * 2)
#define Z_OFF     (AUX_OFF + 1)

// ---------------- scratch (static device globals; no allocs) ----------------
__device__ float    g_Wt[C_DIM * E_DIM];        // W transposed: [k][e]
__device__ uint32_t g_t2i[N_TOK];               // e1 | e2<<8
__device__ float2   g_t2v[N_TOK];               // top2 gate values
__device__ uint32_t g_rank[N_TOK];              // local rank: r0 | r1<<16
__device__ int      g_counts[NCTA * 128];       // per-block bin counts (bin = k*64+e)
__device__ int      g_off[NCTA * 128];          // exclusive scan across blocks
__device__ int      g_tot[128];                 // total per bin
__device__ float    g_mepart[NCTA * E_DIM];     // per-block expert gate sums
__device__ float    g_zpart[NCTA];              // per-block sum of logits^2

// ---------------- K0: transpose W [E,C] -> Wt [C,E] ----------------
__global__ void k_transpose(const float* __restrict__ W) {
    int idx = blockIdx.x * 256 + threadIdx.x;   // 131072 total
    int e = idx >> 11;          // / 2048
    int k = idx & 2047;
    g_Wt[k * E_DIM + e] = W[idx];
}

// ---------------- K1: GEMM + softmax + top2 + local ranks ----------------
// CTA: 256 threads (8 warps), 64 tokens, all 64 experts.
// Group g = warp>>2 handles K half [g*1024, g*1024+1024) with its own smem
// tiles and named barrier (id 1+g, 128 threads). Within a group, warp (w&3)
// handles experts [(w&3)*16, +16); lane owns tokens (lane, lane+32).
// Accumulators are f32x2 packed along the EXPERT dimension (pairs e, e+1).
// Epilogue sums the two groups' logits from smem.
#define FMA2(a, xp, wb) asm("fma.rn.f32x2 %0, %1, %2, %0;" : "+l"(a) : "l"(xp), "l"(wb))

__global__ __launch_bounds__(256) void k_main(const float* __restrict__ x) {
    extern __shared__ __align__(16) float sm[];
    float* xs0 = sm;                                 // [64][65]
    float* xs1 = sm + TOK_PER_CTA * XS_STRIDE;       // [64][65]
    float* wsb = sm + 2 * TOK_PER_CTA * XS_STRIDE;   // ws0,ws1 each [64][64]

    __shared__ float sinv_s[TOK_PER_CTA];
    __shared__ float zrow[TOK_PER_CTA];
    __shared__ int   cnt[256];                       // per-warp(0/1) per-bin counts

    const int tid  = threadIdx.x;
    const int lane = tid & 31;
    const int w    = tid >> 5;
    const int g    = w >> 2;            // K-group 0/1
    const int gtid = tid & 127;
    const int e0   = (w & 3) * 16;
    const int cta  = blockIdx.x;
    const float* xblk = x + (size_t)cta * TOK_PER_CTA * C_DIM;

    float* xsg = g ? xs1 : xs0;
    float* wsg = wsb + g * (KT * E_DIM);
    const int barid = 1 + g;

    unsigned long long acc[16];   // [0..7] token lane, [8..15] token lane+32
#pragma unroll
    for (int i = 0; i < 16; i++) acc[i] = 0ull;

    const int row0 = lane * XS_STRIDE;
    const int row1 = (lane + 32) * XS_STRIDE;

    const int kbeg = g * KHALF;
    for (int kt = kbeg; kt < kbeg + KHALF; kt += KT) {
        // ---- load x tile: 2 threads per token, each 32 consecutive floats ----
        {
            int t = gtid >> 1;
            int half = gtid & 1;
            const float4* src = (const float4*)(xblk + (size_t)t * C_DIM + kt + half * 32);
            float* dst = xsg + t * XS_STRIDE + half * 32;
#pragma unroll
            for (int i = 0; i < 8; i++) {
                float4 v = src[i];
                dst[4*i+0] = v.x; dst[4*i+1] = v.y; dst[4*i+2] = v.z; dst[4*i+3] = v.w;
            }
        }
        // ---- load W tile: KT*64 floats = 1024 float4 across 128 threads ----
        {
            const float4* src = (const float4*)(g_Wt + (size_t)kt * E_DIM);
            float4* dst = (float4*)wsg;
#pragma unroll
            for (int i = 0; i < 8; i++) dst[gtid + i * 128] = src[gtid + i * 128];
        }
        asm volatile("bar.sync %0, 128;" :: "r"(barid) : "memory");

#pragma unroll 2
        for (int k = 0; k < KT; k++) {
            float xa = xsg[row0 + k];
            float xb = xsg[row1 + k];
            unsigned long long xap, xbp;
            asm("mov.b64 %0, {%1, %1};" : "=l"(xap) : "f"(xa));
            asm("mov.b64 %0, {%1, %1};" : "=l"(xbp) : "f"(xb));
            const ulonglong2* wp = (const ulonglong2*)(wsg + k * E_DIM + e0);
            ulonglong2 w0 = wp[0];
            ulonglong2 w1 = wp[1];
            ulonglong2 w2 = wp[2];
            ulonglong2 w3 = wp[3];
            FMA2(acc[0],  xap, w0.x);  FMA2(acc[8],  xbp, w0.x);
            FMA2(acc[1],  xap, w0.y);  FMA2(acc[9],  xbp, w0.y);
            FMA2(acc[2],  xap, w1.x);  FMA2(acc[10], xbp, w1.x);
            FMA2(acc[3],  xap, w1.y);  FMA2(acc[11], xbp, w1.y);
            FMA2(acc[4],  xap, w2.x);  FMA2(acc[12], xbp, w2.x);
            FMA2(acc[5],  xap, w2.y);  FMA2(acc[13], xbp, w2.y);
            FMA2(acc[6],  xap, w3.x);  FMA2(acc[14], xbp, w3.x);
            FMA2(acc[7],  xap, w3.y);  FMA2(acc[15], xbp, w3.y);
        }
        asm volatile("bar.sync %0, 128;" :: "r"(barid) : "memory");
    }

    // ---- write partial logits into this group's xs buffer (reused) ----
#pragma unroll
    for (int p = 0; p < 8; p++) {
        xsg[row0 + e0 + 2*p]     = __uint_as_float((unsigned)(acc[p] & 0xffffffffull));
        xsg[row0 + e0 + 2*p + 1] = __uint_as_float((unsigned)(acc[p] >> 32));
        xsg[row1 + e0 + 2*p]     = __uint_as_float((unsigned)(acc[8+p] & 0xffffffffull));
        xsg[row1 + e0 + 2*p + 1] = __uint_as_float((unsigned)(acc[8+p] >> 32));
    }
    cnt[tid] = 0;   // all 256 bins zeroed deterministically
    __syncthreads();

    // ---- per-token softmax + top2 (threads 0..63, one token each) ----
    int i1 = 0, i2 = 0;
    int r0 = 0, r1 = 0;
    if (tid < 64) {
        float* ra = xs0 + tid * XS_STRIDE;
        const float* rb = xs1 + tid * XS_STRIDE;
        float m = ra[0] + rb[0];
#pragma unroll 4
        for (int e = 1; e < E_DIM; e++) m = fmaxf(m, ra[e] + rb[e]);
        float s = 0.f, z = 0.f;
        float b1 = -1.f, b2 = -1.f;
#pragma unroll 4
        for (int e = 0; e < E_DIM; e++) {
            float l = ra[e] + rb[e];
            z += l * l;
            float v = expf(l - m);
            ra[e] = v;             // overwrite with unnormalized gate
            s += v;
            if (v > b1)      { b2 = b1; i2 = i1; b1 = v; i1 = e; }
            else if (v > b2) { b2 = v; i2 = e; }
        }
        float sinv = 1.f / s;
        sinv_s[tid] = sinv;
        zrow[tid] = z;
        int n = cta * TOK_PER_CTA + tid;
        g_t2v[n] = make_float2(b1 * sinv, b2 * sinv);

        // ---- warp-level deterministic local ranks (token order) ----
        unsigned lt = (1u << lane) - 1u;
        unsigned m0 = __match_any_sync(0xffffffffu, i1);
        r0 = __popc(m0 & lt);
        if ((m0 & lt) == 0) cnt[w * 128 + i1] = __popc(m0);
        unsigned m1 = __match_any_sync(0xffffffffu, i2);
        r1 = __popc(m1 & lt);
        if ((m1 & lt) == 0) cnt[w * 128 + 64 + i2] = __popc(m1);
    }
    __syncthreads();

    if (tid < 64) {
        if (w == 1) {                 // second warp: add first warp's counts
            r0 += cnt[i1];
            r1 += cnt[64 + i2];
        }
        int n = cta * TOK_PER_CTA + tid;
        g_rank[n] = (uint32_t)r0 | ((uint32_t)r1 << 16);
        g_t2i[n]  = (uint32_t)i1 | ((uint32_t)i2 << 8);

        // expert gate-sum partial: sum_t gate[t][e]
        float sme = 0.f;
#pragma unroll 4
        for (int t = 0; t < TOK_PER_CTA; t++)
            sme += xs0[t * XS_STRIDE + tid] * sinv_s[t];
        g_mepart[cta * E_DIM + tid] = sme;
    }
    if (tid < 128)
        g_counts[cta * 128 + tid] = cnt[tid] + cnt[128 + tid];

    if (tid == 0) {
        float zz = 0.f;
        for (int t = 0; t < TOK_PER_CTA; t++) zz += zrow[t];
        g_zpart[cta] = zz;
    }
}

// ---------------- K2a: per-bin parallel exclusive scan over 256 blocks ------
__global__ __launch_bounds__(256) void k_scan_bins() {
    const int b = blockIdx.x;      // 128 bins
    const int t = threadIdx.x;     // 256 = NCTA
    __shared__ int wsum[8];
    __shared__ int woff[8];

    int c = g_counts[t * 128 + b];
    int v = c;
#pragma unroll
    for (int d = 1; d < 32; d <<= 1) {
        int u = __shfl_up_sync(0xffffffffu, v, d);
        if ((t & 31) >= d) v += u;
    }
    if ((t & 31) == 31) wsum[t >> 5] = v;
    __syncthreads();
    if (t == 0) {
        int run = 0;
#pragma unroll
        for (int i = 0; i < 8; i++) { woff[i] = run; run += wsum[i]; }
        g_tot[b] = run;
    }
    __syncthreads();
    g_off[t * 128 + b] = v + woff[t >> 5] - c;   // exclusive
}

// ---------------- K2b: losses ----------------
__global__ __launch_bounds__(256) void k_losses(float* __restrict__ out) {
    __shared__ float red[256];
    const int t = threadIdx.x;
    const int e = t >> 2, q = t & 3;

    // me partial: quarter q sums 64 blocks for expert e
    float s = 0.f;
    for (int blk = q * 64; blk < q * 64 + 64; blk++)
        s += g_mepart[blk * E_DIM + e];
    red[t] = s;
    __syncthreads();

    float a = 0.f;
    if (t < 64) {
        float me = (red[t*4] + red[t*4+1] + red[t*4+2] + red[t*4+3]) * (1.f / (float)N_TOK);
        float ce = (float)g_tot[t] * (1.f / (float)N_TOK);   // top-1 bins are 0..63
        a = (float)E_DIM * me * ce;
    }
    __syncthreads();
    red[t] = (t < 64) ? a : 0.f;
    __syncthreads();
    for (int s2 = 128; s2 > 0; s2 >>= 1) {
        if (t < s2) red[t] += red[t + s2];
        __syncthreads();
    }
    if (t == 0) out[AUX_OFF] = red[0];
    __syncthreads();

    red[t] = g_zpart[t];
    __syncthreads();
    for (int s2 = 128; s2 > 0; s2 >>= 1) {
        if (t < s2) red[t] += red[t + s2];
        __syncthreads();
    }
    if (t == 0) out[Z_OFF] = red[0] * (1.f / ((float)N_TOK * (float)E_DIM));
}

// ---------------- K3: zero + scatter outputs (512 CTAs x 32 tokens) --------
__global__ __launch_bounds__(256) void k_out(float* __restrict__ out) {
    const int cta = blockIdx.x;    // 512 CTAs, 32 tokens each
    const int tid = threadIdx.x;

    float4 z4 = make_float4(0.f, 0.f, 0.f, 0.f);
    float4* dz = (float4*)(out + DISP_OFF + (size_t)cta * 32 * 128);
    float4* cz = (float4*)(out + COMB_OFF + (size_t)cta * 32 * 128);
#pragma unroll
    for (int i = 0; i < 4; i++) {
        dz[tid + i * 256] = z4;
        cz[tid + i * 256] = z4;
    }
    __syncthreads();

    if (tid < 32) {
        int n = cta * 32 + tid;
        uint32_t ii = g_t2i[n];
        int e1 = ii & 0xff, e2 = (ii >> 8) & 0xff;
        uint32_t rr = g_rank[n];
        float2 vv = g_t2v[n];
        int blk64 = n >> 6;                      // original 64-token block id

        int pos0 = g_off[blk64 * 128 + e1]      + (int)(rr & 0xffff);
        int pos1 = g_off[blk64 * 128 + 64 + e2] + (int)(rr >> 16);

        size_t base = (size_t)n * 128;
        if (pos0 < CAP) {
            out[DISP_OFF + base + e1 * 2 + 0] = 1.0f;
            out[COMB_OFF + base + e1 * 2 + 0] = vv.x;
        }
        if (pos1 < CAP) {
            out[DISP_OFF + base + e2 * 2 + 1] = 1.0f;
            out[COMB_OFF + base + e2 * 2 + 1] = vv.y;
        }
    }
}

// ---------------- entry ----------------
#define SMEM_MAIN ((2 * TOK_PER_CTA * XS_STRIDE + 2 * KT * E_DIM) * 4)   // 66048 B

extern "C" void kernel_launch(void* const* d_in, const int* in_sizes, int n_in,
                              void* d_out, int out_size) {
    const float* x = (const float*)d_in[0];   // [4,4096,2048] -> [16384,2048]
    const float* W = (const float*)d_in[1];   // [64,2048]
    float* out = (float*)d_out;

    cudaFuncSetAttribute(k_main, cudaFuncAttributeMaxDynamicSharedMemorySize, SMEM_MAIN);

    k_transpose<<<(C_DIM * E_DIM) / 256, 256>>>(W);
    k_main<<<NCTA, 256, SMEM_MAIN>>>(x);
    k_scan_bins<<<128, 256>>>();
    k_losses<<<1, 256>>>(out);
    k_out<<<512, 256>>>(out);
}

// round 7
// speedup vs baseline: 1.9130x; 1.5341x over previous
#include <cuda_runtime.h>
#include <cstdint>

// Problem constants
#define N_TOK 16384
#define C_DIM 2048
#define E_DIM 64
#define CAP   640                 // int(1.25 * 16384 * 2 / 64)

#define TOK_CTA   128             // tokens per k_main CTA
#define NCTA_MAIN (N_TOK / TOK_CTA)   // 128
#define KT        32              // K-tile
#define NTILE     (C_DIM / KT)    // 64
#define NBLK64    256             // 64-token blocks (rank/scan granularity)

#define XSTR 36                   // xs row stride (floats): 4 mod 32 -> conflict-free frags
#define GSTR 66                   // logits row stride (floats)
#define XS_F (TOK_CTA * XSTR)     // 4608
#define WS_F (E_DIM * XSTR)       // 2304
#define STAGE_F (XS_F + 2 * WS_F) // 9216 floats per stage
#define SMEM_DYN (2 * STAGE_F * 4)    // 73728 B

// Output layout (float32)
#define DISP_OFF  ((size_t)0)
#define COMB_OFF  ((size_t)N_TOK * E_DIM * 2)
#define AUX_OFF   ((size_t)2 * N_TOK * E_DIM * 2)
#define Z_OFF     (AUX_OFF + 1)

// ---------------- scratch (static device globals; no allocs) ----------------
__device__ float    g_Whi[E_DIM * C_DIM];   // tf32 hi part of W [e][k]
__device__ float    g_Wlo[E_DIM * C_DIM];   // tf32 lo part of W [e][k]
__device__ uint32_t g_t2i[N_TOK];           // e1 | e2<<8
__device__ float2   g_t2v[N_TOK];           // top2 gate values
__device__ uint32_t g_rank[N_TOK];          // local rank: r0 | r1<<16
__device__ int      g_counts[NBLK64 * 128]; // per-64tok-block bin counts
__device__ int      g_off[NBLK64 * 128];    // exclusive scan across blocks
__device__ float    g_mepart[NCTA_MAIN * E_DIM];
__device__ float    g_zpart[NCTA_MAIN];

// ---------------- helpers ----------------
__device__ __forceinline__ uint32_t smem_u32(const void* p) {
    return (uint32_t)__cvta_generic_to_shared(p);
}
__device__ __forceinline__ float to_tf32(float x) {
    uint32_t r; asm("cvt.rna.tf32.f32 %0, %1;" : "=r"(r) : "f"(x));
    return __uint_as_float(r);
}
__device__ __forceinline__ void cpa16(uint32_t dst, const void* src) {
    asm volatile("cp.async.cg.shared.global [%0], [%1], 16;"
                 :: "r"(dst), "l"(src) : "memory");
}
__device__ __forceinline__ void mma8(float* d,
                                     uint32_t a0, uint32_t a1, uint32_t a2, uint32_t a3,
                                     uint32_t b0, uint32_t b1) {
    asm volatile(
        "mma.sync.aligned.m16n8k8.row.col.f32.tf32.tf32.f32 "
        "{%0,%1,%2,%3}, {%4,%5,%6,%7}, {%8,%9}, {%0,%1,%2,%3};"
        : "+f"(d[0]), "+f"(d[1]), "+f"(d[2]), "+f"(d[3])
        : "r"(a0), "r"(a1), "r"(a2), "r"(a3), "r"(b0), "r"(b1));
}

// ---------------- K0: split W into tf32 hi/lo ----------------
__global__ __launch_bounds__(256) void k_wsplit(const float* __restrict__ W) {
    int idx = blockIdx.x * 256 + threadIdx.x;   // 131072
    float v = W[idx];
    float h = to_tf32(v);
    g_Whi[idx] = h;
    g_Wlo[idx] = to_tf32(v - h);
}

// ---------------- K1: mma.sync TF32x3 GEMM + softmax + top2 + ranks --------
// 256 threads. Warp w: tokens [w*16, w*16+16), all 64 experts.
// 8 n-tiles of m16n8k8, acc fp32. Double-buffered cp.async K-pipeline.
__global__ __launch_bounds__(256) void k_main(const float* __restrict__ x) {
    extern __shared__ __align__(16) float sm[];
    __shared__ int   cnt[512];          // [half][warp_in_half][128 bins]
    __shared__ float sinv_s[TOK_CTA];
    __shared__ float redz[4];

    const int tid  = threadIdx.x;
    const int lane = tid & 31;
    const int w    = tid >> 5;
    const int cta  = blockIdx.x;
    const uint32_t smb = smem_u32(sm);
    const float* xbase = x + (size_t)cta * TOK_CTA * C_DIM;

#define LOAD_TILE(t) do {                                                     \
    uint32_t sb_ = smb + ((t) & 1) * (STAGE_F * 4);                           \
    const float* xs_ = xbase + (t) * KT;                                      \
    _Pragma("unroll")                                                         \
    for (int c = tid; c < 1024; c += 256) {                                   \
        int row_ = c >> 3, seg_ = c & 7;                                      \
        cpa16(sb_ + (row_ * XSTR + seg_ * 4) * 4,                             \
              xs_ + (size_t)row_ * C_DIM + seg_ * 4);                         \
    }                                                                         \
    const float* wh_ = g_Whi + (t) * KT;                                      \
    const float* wl_ = g_Wlo + (t) * KT;                                      \
    _Pragma("unroll")                                                         \
    for (int c = tid; c < 512; c += 256) {                                    \
        int row_ = c >> 3, seg_ = c & 7;                                      \
        cpa16(sb_ + (XS_F + row_ * XSTR + seg_ * 4) * 4,                      \
              wh_ + (size_t)row_ * C_DIM + seg_ * 4);                         \
        cpa16(sb_ + (XS_F + WS_F + row_ * XSTR + seg_ * 4) * 4,               \
              wl_ + (size_t)row_ * C_DIM + seg_ * 4);                         \
    }                                                                         \
} while (0)

    float acc[8][4];
#pragma unroll
    for (int j = 0; j < 8; j++)
#pragma unroll
        for (int q = 0; q < 4; q++) acc[j][q] = 0.f;

    const int tb = w * 16;
    const int tr = lane >> 2, tc = lane & 3;

    LOAD_TILE(0);
    asm volatile("cp.async.commit_group;" ::: "memory");

    for (int t = 0; t < NTILE; t++) {
        if (t + 1 < NTILE) LOAD_TILE(t + 1);
        asm volatile("cp.async.commit_group;" ::: "memory");
        asm volatile("cp.async.wait_group 1;" ::: "memory");
        __syncthreads();

        const float* st  = sm + (t & 1) * STAGE_F;
        const float* xsA = st + (tb + tr) * XSTR + tc;
        const float* whB = st + XS_F + tr * XSTR + tc;
        const float* wlB = st + XS_F + WS_F + tr * XSTR + tc;

#pragma unroll
        for (int kk = 0; kk < KT; kk += 8) {
            float a0r = xsA[kk];
            float a1r = xsA[8 * XSTR + kk];
            float a2r = xsA[kk + 4];
            float a3r = xsA[8 * XSTR + kk + 4];
            float h0 = to_tf32(a0r), h1 = to_tf32(a1r);
            float h2 = to_tf32(a2r), h3 = to_tf32(a3r);
            uint32_t ah0 = __float_as_uint(h0), ah1 = __float_as_uint(h1);
            uint32_t ah2 = __float_as_uint(h2), ah3 = __float_as_uint(h3);
            uint32_t al0 = __float_as_uint(to_tf32(a0r - h0));
            uint32_t al1 = __float_as_uint(to_tf32(a1r - h1));
            uint32_t al2 = __float_as_uint(to_tf32(a2r - h2));
            uint32_t al3 = __float_as_uint(to_tf32(a3r - h3));

#pragma unroll
            for (int j = 0; j < 8; j++) {
                const float* whj = whB + j * 8 * XSTR + kk;
                const float* wlj = wlB + j * 8 * XSTR + kk;
                uint32_t bh0 = __float_as_uint(whj[0]);
                uint32_t bh1 = __float_as_uint(whj[4]);
                uint32_t bl0 = __float_as_uint(wlj[0]);
                uint32_t bl1 = __float_as_uint(wlj[4]);
                mma8(acc[j], ah0, ah1, ah2, ah3, bh0, bh1);
                mma8(acc[j], ah0, ah1, ah2, ah3, bl0, bl1);
                mma8(acc[j], al0, al1, al2, al3, bh0, bh1);
            }
        }
        __syncthreads();   // protect buffer t&1 before iter t+1 prefetches t+2
    }

    // ---- store logits to smem (stage0 reuse), stride GSTR ----
    float* gsm = sm;
#pragma unroll
    for (int j = 0; j < 8; j++) {
        *(float2*)(gsm + (tb + tr) * GSTR + j * 8 + tc * 2) =
            make_float2(acc[j][0], acc[j][1]);
        *(float2*)(gsm + (tb + tr + 8) * GSTR + j * 8 + tc * 2) =
            make_float2(acc[j][2], acc[j][3]);
    }
    cnt[tid] = 0;
    cnt[tid + 256] = 0;
    __syncthreads();

    // ---- per-token softmax + top2 (threads 0..127, one token each) ----
    int i1 = 0, i2 = 0, r0 = 0, r1 = 0;
    float zsum = 0.f;
    if (w < 4) {
        float* row = gsm + tid * GSTR;
        float m = row[0];
#pragma unroll 4
        for (int e = 1; e < E_DIM; e++) m = fmaxf(m, row[e]);
        float s = 0.f, b1 = -1.f, b2 = -1.f;
#pragma unroll 4
        for (int e = 0; e < E_DIM; e++) {
            float l = row[e];
            zsum += l * l;
            float v = expf(l - m);
            row[e] = v;            // overwrite with unnormalized gate
            s += v;
            if (v > b1)      { b2 = b1; i2 = i1; b1 = v; i1 = e; }
            else if (v > b2) { b2 = v; i2 = e; }
        }
        float sinv = 1.f / s;
        sinv_s[tid] = sinv;
        int n = cta * TOK_CTA + tid;
        g_t2v[n] = make_float2(b1 * sinv, b2 * sinv);

        // deterministic local ranks (token order) within each 64-token half
        int half = w >> 1, wih = w & 1;
        unsigned lt = (1u << lane) - 1u;
        unsigned m0 = __match_any_sync(0xffffffffu, i1);
        r0 = __popc(m0 & lt);
        if ((m0 & lt) == 0) cnt[half * 256 + wih * 128 + i1] = __popc(m0);
        unsigned m1 = __match_any_sync(0xffffffffu, i2);
        r1 = __popc(m1 & lt);
        if ((m1 & lt) == 0) cnt[half * 256 + wih * 128 + 64 + i2] = __popc(m1);
    }
    // z reduce (warps 4..7 contribute zeros)
#pragma unroll
    for (int o = 16; o > 0; o >>= 1) zsum += __shfl_xor_sync(0xffffffffu, zsum, o);
    if (w < 4 && lane == 0) redz[w] = zsum;
    __syncthreads();

    if (w < 4) {
        int half = w >> 1;
        if ((w & 1) == 1) {               // second warp of half adds first warp's counts
            r0 += cnt[half * 256 + i1];
            r1 += cnt[half * 256 + 64 + i2];
        }
        int n = cta * TOK_CTA + tid;
        g_rank[n] = (uint32_t)r0 | ((uint32_t)r1 << 16);
        g_t2i[n]  = (uint32_t)i1 | ((uint32_t)i2 << 8);
    }
    {   // per-64tok-block bin counts (tid covers 256 = 2 halves x 128 bins)
        int half = tid >> 7, b = tid & 127;
        g_counts[(cta * 2 + half) * 128 + b] =
            cnt[half * 256 + b] + cnt[half * 256 + 128 + b];
    }
    if (tid < 64) {
        float sme = 0.f;
        for (int tok = 0; tok < TOK_CTA; tok++)
            sme += gsm[tok * GSTR + tid] * sinv_s[tok];
        g_mepart[cta * 64 + tid] = sme;
    }
    if (tid == 0)
        g_zpart[cta] = redz[0] + redz[1] + redz[2] + redz[3];
#undef LOAD_TILE
}

// ---------------- K2: per-bin scan (blocks 0..127) + losses (block 128) ----
__global__ __launch_bounds__(256) void k_scan(float* __restrict__ out) {
    const int t = threadIdx.x;
    __shared__ int   ired[256];
    __shared__ float fred[256];

    if (blockIdx.x < 128) {
        const int b = blockIdx.x;      // bin
        __shared__ int wsum[8];
        __shared__ int woff[8];
        int c = g_counts[t * 128 + b];
        int v = c;
#pragma unroll
        for (int d = 1; d < 32; d <<= 1) {
            int u = __shfl_up_sync(0xffffffffu, v, d);
            if ((t & 31) >= d) v += u;
        }
        if ((t & 31) == 31) wsum[t >> 5] = v;
        __syncthreads();
        if (t == 0) {
            int run = 0;
#pragma unroll
            for (int i = 0; i < 8; i++) { woff[i] = run; run += wsum[i]; }
        }
        __syncthreads();
        g_off[t * 128 + b] = v + woff[t >> 5] - c;   // exclusive
        return;
    }

    // losses block
    {
        int e = t >> 2, q = t & 3;
        int csum = 0;
        for (int blk = q * 64; blk < q * 64 + 64; blk++)
            csum += g_counts[blk * 128 + e];          // top-1 bins are 0..63
        float msum = 0.f;
        for (int blk = q * 32; blk < q * 32 + 32; blk++)
            msum += g_mepart[blk * 64 + e];
        ired[t] = csum;
        fred[t] = msum;
    }
    __syncthreads();
    float a = 0.f;
    if (t < 64) {
        float me = (fred[4*t] + fred[4*t+1] + fred[4*t+2] + fred[4*t+3]) * (1.f / (float)N_TOK);
        float ce = (float)(ired[4*t] + ired[4*t+1] + ired[4*t+2] + ired[4*t+3]) * (1.f / (float)N_TOK);
        a = (float)E_DIM * me * ce;
    }
    __syncthreads();
    fred[t] = (t < 64) ? a : 0.f;
    __syncthreads();
    for (int s = 128; s > 0; s >>= 1) {
        if (t < s) fred[t] += fred[t + s];
        __syncthreads();
    }
    if (t == 0) out[AUX_OFF] = fred[0];
    __syncthreads();

    fred[t] = (t < NCTA_MAIN) ? g_zpart[t] : 0.f;
    __syncthreads();
    for (int s = 128; s > 0; s >>= 1) {
        if (t < s) fred[t] += fred[t + s];
        __syncthreads();
    }
    if (t == 0) out[Z_OFF] = fred[0] * (1.f / ((float)N_TOK * (float)E_DIM));
}

// ---------------- K3: zero + scatter outputs (512 CTAs x 32 tokens) --------
__global__ __launch_bounds__(256) void k_out(float* __restrict__ out) {
    const int cta = blockIdx.x;
    const int tid = threadIdx.x;

    float4 z4 = make_float4(0.f, 0.f, 0.f, 0.f);
    float4* dz = (float4*)(out + DISP_OFF + (size_t)cta * 32 * 128);
    float4* cz = (float4*)(out + COMB_OFF + (size_t)cta * 32 * 128);
#pragma unroll
    for (int i = 0; i < 4; i++) {
        dz[tid + i * 256] = z4;
        cz[tid + i * 256] = z4;
    }
    __syncthreads();

    if (tid < 32) {
        int n = cta * 32 + tid;
        uint32_t ii = g_t2i[n];
        int e1 = ii & 0xff, e2 = (ii >> 8) & 0xff;
        uint32_t rr = g_rank[n];
        float2 vv = g_t2v[n];
        int blk64 = n >> 6;

        int pos0 = g_off[blk64 * 128 + e1]      + (int)(rr & 0xffff);
        int pos1 = g_off[blk64 * 128 + 64 + e2] + (int)(rr >> 16);

        size_t base = (size_t)n * 128;
        if (pos0 < CAP) {
            out[DISP_OFF + base + e1 * 2 + 0] = 1.0f;
            out[COMB_OFF + base + e1 * 2 + 0] = vv.x;
        }
        if (pos1 < CAP) {
            out[DISP_OFF + base + e2 * 2 + 1] = 1.0f;
            out[COMB_OFF + base + e2 * 2 + 1] = vv.y;
        }
    }
}

// ---------------- entry ----------------
extern "C" void kernel_launch(void* const* d_in, const int* in_sizes, int n_in,
                              void* d_out, int out_size) {
    const float* x = (const float*)d_in[0];   // [16384, 2048]
    const float* W = (const float*)d_in[1];   // [64, 2048]
    float* out = (float*)d_out;

    cudaFuncSetAttribute(k_main, cudaFuncAttributeMaxDynamicSharedMemorySize, SMEM_DYN);

    k_wsplit<<<(E_DIM * C_DIM) / 256, 256>>>(W);
    k_main<<<NCTA_MAIN, 256, SMEM_DYN>>>(x);
    k_scan<<<129, 256>>>(out);
    k_out<<<512, 256>>>(out);
}

// round 8
// speedup vs baseline: 2.7008x; 1.4118x over previous
#include <cuda_runtime.h>
#include <cuda_fp16.h>
#include <cstdint>

// Problem constants
#define N_TOK 16384
#define C_DIM 2048
#define E_DIM 64
#define CAP   640                 // int(1.25 * 16384 * 2 / 64)

#define TOK_CTA   128             // tokens per k_main CTA
#define NCTA_MAIN (N_TOK / TOK_CTA)   // 128
#define KT        32              // K-tile (2 x k16 mma steps)
#define NTILE     (C_DIM / KT)    // 64
#define NBLK64    256             // 64-token blocks (rank/scan granularity)

#define XSTR 40                   // xs row stride (floats): LDS.64 conflict-free
#define BSTR 40                   // W tile row stride (halves): LDS.32 conflict-free
#define GSTR 66                   // logits row stride (floats)

#define XS_BYTES (TOK_CTA * XSTR * 4)     // 20480
#define WH_BYTES (E_DIM * BSTR * 2)       // 5120
#define STAGE_B  (XS_BYTES + 2 * WH_BYTES)    // 30720
#define SMEM_DYN (2 * STAGE_B)                // 61440

#define INV1024 0.0009765625f

// Output layout (float32)
#define DISP_OFF  ((size_t)0)
#define COMB_OFF  ((size_t)N_TOK * E_DIM * 2)
#define AUX_OFF   ((size_t)2 * N_TOK * E_DIM * 2)
#define Z_OFF     (AUX_OFF + 1)

// ---------------- scratch (static device globals; no allocs) ----------------
__device__ __half   g_Whh[E_DIM * C_DIM];   // fp16 hi part of W [e][k]
__device__ __half   g_Whl[E_DIM * C_DIM];   // fp16 (lo part * 1024)
__device__ uint32_t g_t2i[N_TOK];           // e1 | e2<<8
__device__ float2   g_t2v[N_TOK];           // top2 gate values
__device__ uint32_t g_rank[N_TOK];          // local rank: r0 | r1<<16
__device__ int      g_counts[NBLK64 * 128]; // per-64tok-block bin counts
__device__ int      g_off[NBLK64 * 128];    // exclusive scan across blocks
__device__ float    g_mepart[NCTA_MAIN * E_DIM];
__device__ float    g_zpart[NCTA_MAIN];

// ---------------- helpers ----------------
__device__ __forceinline__ uint32_t smem_u32(const void* p) {
    return (uint32_t)__cvta_generic_to_shared(p);
}
__device__ __forceinline__ void cpa16(uint32_t dst, const void* src) {
    asm volatile("cp.async.cg.shared.global [%0], [%1], 16;"
                 :: "r"(dst), "l"(src) : "memory");
}
__device__ __forceinline__ void mma16(float* d,
                                      uint32_t a0, uint32_t a1, uint32_t a2, uint32_t a3,
                                      uint32_t b0, uint32_t b1) {
    asm volatile(
        "mma.sync.aligned.m16n8k16.row.col.f32.f16.f16.f32 "
        "{%0,%1,%2,%3}, {%4,%5,%6,%7}, {%8,%9}, {%0,%1,%2,%3};"
        : "+f"(d[0]), "+f"(d[1]), "+f"(d[2]), "+f"(d[3])
        : "r"(a0), "r"(a1), "r"(a2), "r"(a3), "r"(b0), "r"(b1));
}
// split float2 -> (hi half2, lo half2); lo NOT scaled
__device__ __forceinline__ void split2(float2 v, uint32_t& h, uint32_t& l) {
    __half2 hh = __floats2half2_rn(v.x, v.y);
    float2 hf = __half22float2(hh);
    __half2 ll = __floats2half2_rn(v.x - hf.x, v.y - hf.y);
    h = *(uint32_t*)&hh;
    l = *(uint32_t*)&ll;
}

// ---------------- K0: split W into fp16 hi / (lo*1024) ----------------
__global__ __launch_bounds__(256) void k_wsplit(const float* __restrict__ W) {
    int idx = blockIdx.x * 256 + threadIdx.x;   // 131072
    float v = W[idx];
    __half h = __float2half_rn(v);
    g_Whh[idx] = h;
    g_Whl[idx] = __float2half_rn((v - __half2float(h)) * 1024.0f);
}

// ---------------- K1: mma.sync fp16-split GEMM + softmax + top2 + ranks ----
// 256 threads. Warp w: tokens [w*16, w*16+16), all 64 experts.
// 8 n-tiles of m16n8k16; accM = (xh+xl)*wh, accL = xh*(wl*1024).
__global__ __launch_bounds__(256) void k_main(const float* __restrict__ x) {
    extern __shared__ __align__(16) char smc[];
    __shared__ int   cnt[512];          // [half][warp_in_half][128 bins]
    __shared__ float sinv_s[TOK_CTA];
    __shared__ float redz[4];

    const int tid  = threadIdx.x;
    const int lane = tid & 31;
    const int w    = tid >> 5;
    const int cta  = blockIdx.x;
    const uint32_t smb = smem_u32(smc);
    const float* xbase = x + (size_t)cta * TOK_CTA * C_DIM;

#define LOAD_TILE(t) do {                                                     \
    uint32_t sb_ = smb + ((t) & 1) * STAGE_B;                                 \
    const float* xs_ = xbase + (t) * KT;                                      \
    _Pragma("unroll")                                                         \
    for (int c = tid; c < 1024; c += 256) {                                   \
        int row_ = c >> 3, seg_ = c & 7;                                      \
        cpa16(sb_ + (uint32_t)(row_ * (XSTR * 4) + seg_ * 16),                \
              xs_ + (size_t)row_ * C_DIM + seg_ * 4);                         \
    }                                                                         \
    {                                                                         \
        int row_ = tid >> 2, seg_ = tid & 3;                                  \
        const __half* wh_ = g_Whh + (size_t)row_ * C_DIM + (t) * KT + seg_ * 8;\
        const __half* wl_ = g_Whl + (size_t)row_ * C_DIM + (t) * KT + seg_ * 8;\
        cpa16(sb_ + XS_BYTES + (uint32_t)(row_ * (BSTR * 2) + seg_ * 16), wh_);\
        cpa16(sb_ + XS_BYTES + WH_BYTES + (uint32_t)(row_ * (BSTR * 2) + seg_ * 16), wl_);\
    }                                                                         \
} while (0)

    float accM[8][4], accL[8][4];
#pragma unroll
    for (int j = 0; j < 8; j++)
#pragma unroll
        for (int q = 0; q < 4; q++) { accM[j][q] = 0.f; accL[j][q] = 0.f; }

    const int tb = w * 16;
    const int tr = lane >> 2, tc = lane & 3;

    LOAD_TILE(0);
    asm volatile("cp.async.commit_group;" ::: "memory");

    for (int t = 0; t < NTILE; t++) {
        if (t + 1 < NTILE) LOAD_TILE(t + 1);
        asm volatile("cp.async.commit_group;" ::: "memory");
        asm volatile("cp.async.wait_group 1;" ::: "memory");
        __syncthreads();

        const char* st = smc + (t & 1) * STAGE_B;
        const float* xsA = (const float*)st + (tb + tr) * XSTR + 2 * tc;
        const __half* whB = (const __half*)(st + XS_BYTES) + tr * BSTR + 2 * tc;
        const __half* wlB = (const __half*)(st + XS_BYTES + WH_BYTES) + tr * BSTR + 2 * tc;

#pragma unroll
        for (int kk = 0; kk < KT; kk += 16) {
            // A fragments: rows tr/tr+8 of this warp's 16 tokens, cols kk+2tc(+1), +8
            float2 v0 = *(const float2*)(xsA + kk);                 // (r, c)
            float2 v1 = *(const float2*)(xsA + 8 * XSTR + kk);      // (r+8, c)
            float2 v2 = *(const float2*)(xsA + kk + 8);             // (r, c+8)
            float2 v3 = *(const float2*)(xsA + 8 * XSTR + kk + 8);  // (r+8, c+8)
            uint32_t ah0, al0, ah1, al1, ah2, al2, ah3, al3;
            split2(v0, ah0, al0);
            split2(v1, ah1, al1);
            split2(v2, ah2, al2);
            split2(v3, ah3, al3);

#pragma unroll
            for (int j = 0; j < 8; j++) {
                const __half* whj = whB + j * 8 * BSTR + kk;
                const __half* wlj = wlB + j * 8 * BSTR + kk;
                uint32_t bh0 = *(const uint32_t*)whj;
                uint32_t bh1 = *(const uint32_t*)(whj + 8);
                uint32_t bl0 = *(const uint32_t*)wlj;
                uint32_t bl1 = *(const uint32_t*)(wlj + 8);
                mma16(accM[j], ah0, ah1, ah2, ah3, bh0, bh1);
                mma16(accM[j], al0, al1, al2, al3, bh0, bh1);
                mma16(accL[j], ah0, ah1, ah2, ah3, bl0, bl1);
            }
        }
        __syncthreads();   // protect buffer t&1 before iter t+1 prefetches t+2
    }

    // ---- combine + store logits to smem (stage0 reuse), stride GSTR ----
    float* gsm = (float*)smc;
    __syncthreads();
#pragma unroll
    for (int j = 0; j < 8; j++) {
        float l0 = accM[j][0] + accL[j][0] * INV1024;
        float l1 = accM[j][1] + accL[j][1] * INV1024;
        float l2 = accM[j][2] + accL[j][2] * INV1024;
        float l3 = accM[j][3] + accL[j][3] * INV1024;
        *(float2*)(gsm + (tb + tr) * GSTR + j * 8 + tc * 2) = make_float2(l0, l1);
        *(float2*)(gsm + (tb + tr + 8) * GSTR + j * 8 + tc * 2) = make_float2(l2, l3);
    }
    cnt[tid] = 0;
    cnt[tid + 256] = 0;
    __syncthreads();

    // ---- per-token softmax + top2 (threads 0..127, one token each) ----
    int i1 = 0, i2 = 0, r0 = 0, r1 = 0;
    float zsum = 0.f;
    if (w < 4) {
        float* row = gsm + tid * GSTR;
        float m = row[0];
#pragma unroll 4
        for (int e = 1; e < E_DIM; e++) m = fmaxf(m, row[e]);
        float s = 0.f, b1 = -1.f, b2 = -1.f;
#pragma unroll 4
        for (int e = 0; e < E_DIM; e++) {
            float l = row[e];
            zsum += l * l;
            float v = expf(l - m);
            row[e] = v;            // overwrite with unnormalized gate
            s += v;
            if (v > b1)      { b2 = b1; i2 = i1; b1 = v; i1 = e; }
            else if (v > b2) { b2 = v; i2 = e; }
        }
        float sinv = 1.f / s;
        sinv_s[tid] = sinv;
        int n = cta * TOK_CTA + tid;
        g_t2v[n] = make_float2(b1 * sinv, b2 * sinv);

        // deterministic local ranks (token order) within each 64-token half
        int half = w >> 1, wih = w & 1;
        unsigned lt = (1u << lane) - 1u;
        unsigned m0 = __match_any_sync(0xffffffffu, i1);
        r0 = __popc(m0 & lt);
        if ((m0 & lt) == 0) cnt[half * 256 + wih * 128 + i1] = __popc(m0);
        unsigned m1 = __match_any_sync(0xffffffffu, i2);
        r1 = __popc(m1 & lt);
        if ((m1 & lt) == 0) cnt[half * 256 + wih * 128 + 64 + i2] = __popc(m1);
    }
    // z reduce (warps 4..7 contribute zeros)
#pragma unroll
    for (int o = 16; o > 0; o >>= 1) zsum += __shfl_xor_sync(0xffffffffu, zsum, o);
    if (w < 4 && lane == 0) redz[w] = zsum;
    __syncthreads();

    if (w < 4) {
        int half = w >> 1;
        if ((w & 1) == 1) {               // second warp of half adds first warp's counts
            r0 += cnt[half * 256 + i1];
            r1 += cnt[half * 256 + 64 + i2];
        }
        int n = cta * TOK_CTA + tid;
        g_rank[n] = (uint32_t)r0 | ((uint32_t)r1 << 16);
        g_t2i[n]  = (uint32_t)i1 | ((uint32_t)i2 << 8);
    }
    {   // per-64tok-block bin counts (tid covers 256 = 2 halves x 128 bins)
        int half = tid >> 7, b = tid & 127;
        g_counts[(cta * 2 + half) * 128 + b] =
            cnt[half * 256 + b] + cnt[half * 256 + 128 + b];
    }
    if (tid < 64) {
        float sme = 0.f;
        for (int tok = 0; tok < TOK_CTA; tok++)
            sme += gsm[tok * GSTR + tid] * sinv_s[tok];
        g_mepart[cta * 64 + tid] = sme;
    }
    if (tid == 0)
        g_zpart[cta] = redz[0] + redz[1] + redz[2] + redz[3];
#undef LOAD_TILE
}

// ---------------- K2: per-bin scan (blocks 0..127) + losses (block 128) ----
__global__ __launch_bounds__(256) void k_scan(float* __restrict__ out) {
    const int t = threadIdx.x;
    __shared__ int   ired[256];
    __shared__ float fred[256];

    if (blockIdx.x < 128) {
        const int b = blockIdx.x;      // bin
        __shared__ int wsum[8];
        __shared__ int woff[8];
        int c = g_counts[t * 128 + b];
        int v = c;
#pragma unroll
        for (int d = 1; d < 32; d <<= 1) {
            int u = __shfl_up_sync(0xffffffffu, v, d);
            if ((t & 31) >= d) v += u;
        }
        if ((t & 31) == 31) wsum[t >> 5] = v;
        __syncthreads();
        if (t == 0) {
            int run = 0;
#pragma unroll
            for (int i = 0; i < 8; i++) { woff[i] = run; run += wsum[i]; }
        }
        __syncthreads();
        g_off[t * 128 + b] = v + woff[t >> 5] - c;   // exclusive
        return;
    }

    // losses block
    {
        int e = t >> 2, q = t & 3;
        int csum = 0;
        for (int blk = q * 64; blk < q * 64 + 64; blk++)
            csum += g_counts[blk * 128 + e];          // top-1 bins are 0..63
        float msum = 0.f;
        for (int blk = q * 32; blk < q * 32 + 32; blk++)
            msum += g_mepart[blk * 64 + e];
        ired[t] = csum;
        fred[t] = msum;
    }
    __syncthreads();
    float a = 0.f;
    if (t < 64) {
        float me = (fred[4*t] + fred[4*t+1] + fred[4*t+2] + fred[4*t+3]) * (1.f / (float)N_TOK);
        float ce = (float)(ired[4*t] + ired[4*t+1] + ired[4*t+2] + ired[4*t+3]) * (1.f / (float)N_TOK);
        a = (float)E_DIM * me * ce;
    }
    __syncthreads();
    fred[t] = (t < 64) ? a : 0.f;
    __syncthreads();
    for (int s = 128; s > 0; s >>= 1) {
        if (t < s) fred[t] += fred[t + s];
        __syncthreads();
    }
    if (t == 0) out[AUX_OFF] = fred[0];
    __syncthreads();

    fred[t] = (t < NCTA_MAIN) ? g_zpart[t] : 0.f;
    __syncthreads();
    for (int s = 128; s > 0; s >>= 1) {
        if (t < s) fred[t] += fred[t + s];
        __syncthreads();
    }
    if (t == 0) out[Z_OFF] = fred[0] * (1.f / ((float)N_TOK * (float)E_DIM));
}

// ---------------- K3: zero + scatter outputs (1024 CTAs x 16 tokens) -------
__global__ __launch_bounds__(256) void k_out(float* __restrict__ out) {
    const int cta = blockIdx.x;
    const int tid = threadIdx.x;

    float4 z4 = make_float4(0.f, 0.f, 0.f, 0.f);
    float4* dz = (float4*)(out + DISP_OFF + (size_t)cta * 16 * 128);
    float4* cz = (float4*)(out + COMB_OFF + (size_t)cta * 16 * 128);
#pragma unroll
    for (int i = 0; i < 2; i++) {
        dz[tid + i * 256] = z4;
        cz[tid + i * 256] = z4;
    }
    __syncthreads();

    if (tid < 16) {
        int n = cta * 16 + tid;
        uint32_t ii = g_t2i[n];
        int e1 = ii & 0xff, e2 = (ii >> 8) & 0xff;
        uint32_t rr = g_rank[n];
        float2 vv = g_t2v[n];
        int blk64 = n >> 6;

        int pos0 = g_off[blk64 * 128 + e1]      + (int)(rr & 0xffff);
        int pos1 = g_off[blk64 * 128 + 64 + e2] + (int)(rr >> 16);

        size_t base = (size_t)n * 128;
        if (pos0 < CAP) {
            out[DISP_OFF + base + e1 * 2 + 0] = 1.0f;
            out[COMB_OFF + base + e1 * 2 + 0] = vv.x;
        }
        if (pos1 < CAP) {
            out[DISP_OFF + base + e2 * 2 + 1] = 1.0f;
            out[COMB_OFF + base + e2 * 2 + 1] = vv.y;
        }
    }
}

// ---------------- entry ----------------
extern "C" void kernel_launch(void* const* d_in, const int* in_sizes, int n_in,
                              void* d_out, int out_size) {
    const float* x = (const float*)d_in[0];   // [16384, 2048]
    const float* W = (const float*)d_in[1];   // [64, 2048]
    float* out = (float*)d_out;

    cudaFuncSetAttribute(k_main, cudaFuncAttributeMaxDynamicSharedMemorySize, SMEM_DYN);

    k_wsplit<<<(E_DIM * C_DIM) / 256, 256>>>(W);
    k_main<<<NCTA_MAIN, 256, SMEM_DYN>>>(x);
    k_scan<<<129, 256>>>(out);
    k_out<<<1024, 256>>>(out);
}